// round 2
// baseline (speedup 1.0000x reference)
#include <cuda_runtime.h>
#include <math.h>

// Net_R1L: single-layer ReLU RNN, B=4096, T=2048, NIN=3, NHID=5, NOUT=1
//
// Round 2: the recurrence is latency-bound per warp (R1: issue 18.8% chip,
// fma ~21% per occupied SMSP, ~190 cyc/step vs ~54-cyc fma-rt floor).
// Fix: 2 independent batch chains per thread -> guaranteed ILP fills the
// dependency-chain bubbles. 2048 threads = 64 warps, each warp advances two
// recurrences; per-warp rate -> fma-throughput bound (~55-60 cyc/chain-step).
// Also: slim register staging (4-step tiles, no triple buffering) and split
// each recurrent dot into two sub-chains merged with add.rn.f32x2 so the
// loop-carried path is ~25 cyc (pack -> 3x ffma2 -> add -> fmax).

#define TT 2048
#define NINPUT 3
#define NH 5
#define CPT 2   // chains (batch rows) per thread

typedef unsigned long long u64;

static __device__ __forceinline__ u64 pack2(float lo, float hi) {
    u64 r;
    asm("mov.b64 %0, {%1, %2};" : "=l"(r) : "f"(lo), "f"(hi));
    return r;
}
static __device__ __forceinline__ void unpack2(u64 v, float& lo, float& hi) {
    asm("mov.b64 {%0, %1}, %2;" : "=f"(lo), "=f"(hi) : "l"(v));
}
static __device__ __forceinline__ u64 ffma2(u64 a, u64 b, u64 c) {
    u64 d;
    asm("fma.rn.f32x2 %0, %1, %2, %3;" : "=l"(d) : "l"(a), "l"(b), "l"(c));
    return d;
}
static __device__ __forceinline__ u64 fmul2(u64 a, u64 b) {
    u64 d;
    asm("mul.rn.f32x2 %0, %1, %2;" : "=l"(d) : "l"(a), "l"(b));
    return d;
}
static __device__ __forceinline__ u64 fadd2(u64 a, u64 b) {
    u64 d;
    asm("add.rn.f32x2 %0, %1, %2;" : "=l"(d) : "l"(a), "l"(b));
    return d;
}

struct Weights {
    u64 wih01[NINPUT], wih23[NINPUT];
    float wih4[NINPUT];
    u64 whh01[NH], whh23[NH];
    float whh4[NH];
    u64 c01, c23;
    float c4;
};

// One RNN step for one chain. x0..x2 inputs, h[5] in/out.
static __device__ __forceinline__ void rnn_step(
    const Weights& W, float x0, float x1, float x2, float h[NH])
{
    // x-proj prefix (independent of h, schedulable early)
    const u64 xd0 = pack2(x0, x0);
    const u64 xd1 = pack2(x1, x1);
    const u64 xd2 = pack2(x2, x2);

    u64 t01 = ffma2(xd0, W.wih01[0], W.c01);
    u64 t23 = ffma2(xd0, W.wih23[0], W.c23);
    float t4 = fmaf(x0, W.wih4[0], W.c4);
    t01 = ffma2(xd1, W.wih01[1], t01);
    t23 = ffma2(xd1, W.wih23[1], t23);
    t4  = fmaf(x1, W.wih4[1], t4);
    t01 = ffma2(xd2, W.wih01[2], t01);
    t23 = ffma2(xd2, W.wih23[2], t23);
    t4  = fmaf(x2, W.wih4[2], t4);

    // recurrent part: split into two sub-chains per output pair
    const u64 hd0 = pack2(h[0], h[0]);
    const u64 hd1 = pack2(h[1], h[1]);
    const u64 hd2 = pack2(h[2], h[2]);
    const u64 hd3 = pack2(h[3], h[3]);
    const u64 hd4 = pack2(h[4], h[4]);

    u64 a01 = ffma2(hd0, W.whh01[0], t01);
    a01 = ffma2(hd1, W.whh01[1], a01);
    a01 = ffma2(hd2, W.whh01[2], a01);
    u64 b01 = fmul2(hd3, W.whh01[3]);
    b01 = ffma2(hd4, W.whh01[4], b01);
    a01 = fadd2(a01, b01);

    u64 a23 = ffma2(hd0, W.whh23[0], t23);
    a23 = ffma2(hd1, W.whh23[1], a23);
    a23 = ffma2(hd2, W.whh23[2], a23);
    u64 b23 = fmul2(hd3, W.whh23[3]);
    b23 = ffma2(hd4, W.whh23[4], b23);
    a23 = fadd2(a23, b23);

    float a4 = fmaf(h[0], W.whh4[0], t4);
    a4 = fmaf(h[1], W.whh4[1], a4);
    a4 = fmaf(h[2], W.whh4[2], a4);
    float b4 = h[3] * W.whh4[3];
    b4 = fmaf(h[4], W.whh4[4], b4);
    a4 = a4 + b4;

    float p0, p1, p2, p3;
    unpack2(a01, p0, p1);
    unpack2(a23, p2, p3);
    h[0] = fmaxf(p0, 0.0f);
    h[1] = fmaxf(p1, 0.0f);
    h[2] = fmaxf(p2, 0.0f);
    h[3] = fmaxf(p3, 0.0f);
    h[4] = fmaxf(a4, 0.0f);
}

__global__ void __launch_bounds__(32, 1) rnn_relu_kernel(
    const float* __restrict__ state,   // [B, T, 3]
    const float* __restrict__ W_ih,    // [5, 3]
    const float* __restrict__ W_hh,    // [5, 5]
    const float* __restrict__ b_ih,    // [5]
    const float* __restrict__ b_hh,    // [5]
    const float* __restrict__ W_out,   // [1, 5]
    const float* __restrict__ b_out,   // [1]
    float* __restrict__ out,           // [B, 1]
    int B)
{
    const int nthreads = B / CPT;
    const int gid = blockIdx.x * 32 + threadIdx.x;
    if (gid >= nthreads) return;

    const int b0 = gid;
    const int b1 = gid + nthreads;

    // ---- Load and pack weights ----
    Weights W;
    {
        float wih_s[NH][NINPUT], whh_s[NH][NH], c_s[NH];
#pragma unroll
        for (int j = 0; j < NH; j++) {
#pragma unroll
            for (int i = 0; i < NINPUT; i++) wih_s[j][i] = __ldg(&W_ih[j * NINPUT + i]);
#pragma unroll
            for (int k = 0; k < NH; k++) whh_s[j][k] = __ldg(&W_hh[j * NH + k]);
            c_s[j] = __ldg(&b_ih[j]) + __ldg(&b_hh[j]);
        }
#pragma unroll
        for (int i = 0; i < NINPUT; i++) {
            W.wih01[i] = pack2(wih_s[0][i], wih_s[1][i]);
            W.wih23[i] = pack2(wih_s[2][i], wih_s[3][i]);
            W.wih4[i]  = wih_s[4][i];
        }
#pragma unroll
        for (int k = 0; k < NH; k++) {
            W.whh01[k] = pack2(whh_s[0][k], whh_s[1][k]);
            W.whh23[k] = pack2(whh_s[2][k], whh_s[3][k]);
            W.whh4[k]  = whh_s[4][k];
        }
        W.c01 = pack2(c_s[0], c_s[1]);
        W.c23 = pack2(c_s[2], c_s[3]);
        W.c4  = c_s[4];
    }

    float hA[NH], hB[NH];
#pragma unroll
    for (int k = 0; k < NH; k++) { hA[k] = 0.0f; hB[k] = 0.0f; }

    // x rows: contiguous 24 KB each. 4 steps = 12 floats = 3 float4.
    const float4* __restrict__ xrA =
        (const float4*)(state + (size_t)b0 * (size_t)(TT * NINPUT));
    const float4* __restrict__ xrB =
        (const float4*)(state + (size_t)b1 * (size_t)(TT * NINPUT));
    const int NTILES = TT / 4;  // 512

    float4 bufA[3], bufB[3];
#pragma unroll
    for (int i = 0; i < 3; i++) { bufA[i] = xrA[i]; bufB[i] = xrB[i]; }

    for (int tile = 0; tile < NTILES; ++tile) {
        // unpack current tile into flat regs
        float xA[12], xB[12];
#pragma unroll
        for (int i = 0; i < 3; i++) {
            xA[4*i+0] = bufA[i].x; xA[4*i+1] = bufA[i].y;
            xA[4*i+2] = bufA[i].z; xA[4*i+3] = bufA[i].w;
            xB[4*i+0] = bufB[i].x; xB[4*i+1] = bufB[i].y;
            xB[4*i+2] = bufB[i].z; xB[4*i+3] = bufB[i].w;
        }

        // prefetch next tile (clamped)
        const int nt = (tile + 1 < NTILES) ? (tile + 1) : tile;
#pragma unroll
        for (int i = 0; i < 3; i++) {
            bufA[i] = xrA[(size_t)nt * 3 + i];
            bufB[i] = xrB[(size_t)nt * 3 + i];
        }

#pragma unroll
        for (int s = 0; s < 4; ++s) {
            rnn_step(W, xA[3*s+0], xA[3*s+1], xA[3*s+2], hA);
            rnn_step(W, xB[3*s+0], xB[3*s+1], xB[3*s+2], hB);
        }
    }

    // ---- Readout ----
    float oA = __ldg(&b_out[0]);
    float oB = oA;
#pragma unroll
    for (int k = 0; k < NH; k++) {
        const float wo = __ldg(&W_out[k]);
        oA = fmaf(hA[k], wo, oA);
        oB = fmaf(hB[k], wo, oB);
    }
    out[b0] = tanhf(oA);
    out[b1] = tanhf(oB);
}

extern "C" void kernel_launch(void* const* d_in, const int* in_sizes, int n_in,
                              void* d_out, int out_size)
{
    const float* state = (const float*)d_in[0];
    const float* W_ih  = (const float*)d_in[1];
    const float* W_hh  = (const float*)d_in[2];
    const float* b_ih  = (const float*)d_in[3];
    const float* b_hh  = (const float*)d_in[4];
    const float* W_out = (const float*)d_in[5];
    const float* b_out = (const float*)d_in[6];
    float* out = (float*)d_out;

    const int B = in_sizes[0] / (TT * NINPUT);  // 4096
    const int nthreads = B / CPT;               // 2048
    const int threads = 32;
    const int blocks = (nthreads + threads - 1) / threads;  // 64

    rnn_relu_kernel<<<blocks, threads>>>(state, W_ih, W_hh, b_ih, b_hh,
                                         W_out, b_out, out, B);
}

// round 3
// speedup vs baseline: 2.1037x; 2.1037x over previous
#include <cuda_runtime.h>
#include <math.h>

// Net_R1L: single-layer ReLU RNN, B=4096, T=2048, NIN=3, NHID=5, NOUT=1
//
// Round 3: R1/R2 showed warps issue at ~87% of cycles — the kernel is
// ISSUE-bound, and the f32x2 inline-PTX packing bloated SASS ~3x with
// register-pair MOV shuffling (150 regs, ~150 instr/step). Fix: plain scalar
// fp32 FFMA (ptxas-native, zero operand shuffling), 1 chain per thread,
// 128 warps on 128 SMs. ~48 issue slots/step -> ~50 cyc/step.
// Loop-carried path (h -> 5-deep FFMA chain -> FMNMX ~ 24 cyc) stays under
// the issue window, so throughput = instruction count.
// x streamed as 8-step tiles (6 float4, 96B) with explicit ping-pong buffers
// (no cur/xs copy arrays) and 1-tile-ahead prefetch.

#define TT 2048
#define NINPUT 3
#define NH 5

// Compile-time float4-component extraction (idx must be a literal in an
// unrolled context).
#define XC(buf, idx) \
    ((idx) % 4 == 0 ? (buf)[(idx) / 4].x : \
     (idx) % 4 == 1 ? (buf)[(idx) / 4].y : \
     (idx) % 4 == 2 ? (buf)[(idx) / 4].z : (buf)[(idx) / 4].w)

struct Weights {
    float wih[NH][NINPUT];  // W_ih[j][i]
    float whh[NH][NH];      // W_hh[j][k]
    float c[NH];            // b_ih + b_hh
};

// One RNN step: h = relu(c + x W_ih^T + h W_hh^T), scalar FFMAs only.
static __device__ __forceinline__ void rnn_step(
    const Weights& W, float x0, float x1, float x2, float h[NH])
{
    float a[NH];
#pragma unroll
    for (int j = 0; j < NH; j++) {
        float t = fmaf(x0, W.wih[j][0], W.c[j]);
        t = fmaf(x1, W.wih[j][1], t);
        t = fmaf(x2, W.wih[j][2], t);
        t = fmaf(h[0], W.whh[j][0], t);
        t = fmaf(h[1], W.whh[j][1], t);
        t = fmaf(h[2], W.whh[j][2], t);
        t = fmaf(h[3], W.whh[j][3], t);
        t = fmaf(h[4], W.whh[j][4], t);
        a[j] = t;
    }
#pragma unroll
    for (int j = 0; j < NH; j++) h[j] = fmaxf(a[j], 0.0f);
}

// 8 steps from a 6-float4 tile buffer.
static __device__ __forceinline__ void do_tile(
    const Weights& W, const float4 buf[6], float h[NH])
{
    rnn_step(W, XC(buf, 0),  XC(buf, 1),  XC(buf, 2),  h);
    rnn_step(W, XC(buf, 3),  XC(buf, 4),  XC(buf, 5),  h);
    rnn_step(W, XC(buf, 6),  XC(buf, 7),  XC(buf, 8),  h);
    rnn_step(W, XC(buf, 9),  XC(buf, 10), XC(buf, 11), h);
    rnn_step(W, XC(buf, 12), XC(buf, 13), XC(buf, 14), h);
    rnn_step(W, XC(buf, 15), XC(buf, 16), XC(buf, 17), h);
    rnn_step(W, XC(buf, 18), XC(buf, 19), XC(buf, 20), h);
    rnn_step(W, XC(buf, 21), XC(buf, 22), XC(buf, 23), h);
}

__global__ void __launch_bounds__(32, 1) rnn_relu_kernel(
    const float* __restrict__ state,   // [B, T, 3]
    const float* __restrict__ W_ih,    // [5, 3]
    const float* __restrict__ W_hh,    // [5, 5]
    const float* __restrict__ b_ih,    // [5]
    const float* __restrict__ b_hh,    // [5]
    const float* __restrict__ W_out,   // [1, 5]
    const float* __restrict__ b_out,   // [1]
    float* __restrict__ out,           // [B, 1]
    int B)
{
    const int b = blockIdx.x * 32 + threadIdx.x;
    if (b >= B) return;

    Weights W;
#pragma unroll
    for (int j = 0; j < NH; j++) {
#pragma unroll
        for (int i = 0; i < NINPUT; i++) W.wih[j][i] = __ldg(&W_ih[j * NINPUT + i]);
#pragma unroll
        for (int k = 0; k < NH; k++) W.whh[j][k] = __ldg(&W_hh[j * NH + k]);
        W.c[j] = __ldg(&b_ih[j]) + __ldg(&b_hh[j]);
    }

    float h[NH];
#pragma unroll
    for (int k = 0; k < NH; k++) h[k] = 0.0f;

    // This thread's x row: contiguous 24 KB, 16B-aligned.
    // Tile = 8 steps = 24 floats = 6 float4. 256 tiles (even count).
    const float4* __restrict__ xr =
        (const float4*)(state + (size_t)b * (size_t)(TT * NINPUT));
    const int NTILES = TT / 8;  // 256

    float4 bufA[6], bufB[6];
#pragma unroll
    for (int i = 0; i < 6; i++) bufA[i] = xr[i];

    for (int t = 0; t < NTILES; t += 2) {
        // prefetch tile t+1 into B, compute tile t from A
        const size_t o1 = (size_t)(t + 1) * 6;
#pragma unroll
        for (int i = 0; i < 6; i++) bufB[i] = xr[o1 + i];
        do_tile(W, bufA, h);

        // prefetch tile t+2 into A (clamped on the last pair), compute t+1 from B
        const int n2 = (t + 2 < NTILES) ? (t + 2) : t;
        const size_t o2 = (size_t)n2 * 6;
#pragma unroll
        for (int i = 0; i < 6; i++) bufA[i] = xr[o2 + i];
        do_tile(W, bufB, h);
    }

    // Readout: tanh(W_out @ h_T + b_out)
    float o = __ldg(&b_out[0]);
#pragma unroll
    for (int k = 0; k < NH; k++) o = fmaf(h[k], __ldg(&W_out[k]), o);
    out[b] = tanhf(o);
}

extern "C" void kernel_launch(void* const* d_in, const int* in_sizes, int n_in,
                              void* d_out, int out_size)
{
    const float* state = (const float*)d_in[0];
    const float* W_ih  = (const float*)d_in[1];
    const float* W_hh  = (const float*)d_in[2];
    const float* b_ih  = (const float*)d_in[3];
    const float* b_hh  = (const float*)d_in[4];
    const float* W_out = (const float*)d_in[5];
    const float* b_out = (const float*)d_in[6];
    float* out = (float*)d_out;

    const int B = in_sizes[0] / (TT * NINPUT);  // 4096
    const int threads = 32;
    const int blocks = (B + threads - 1) / threads;  // 128

    rnn_relu_kernel<<<blocks, threads>>>(state, W_ih, W_hh, b_ih, b_hh,
                                         W_out, b_out, out, B);
}

// round 4
// speedup vs baseline: 4.1106x; 1.9540x over previous
#include <cuda_runtime.h>
#include <math.h>
#include <stdint.h>

// Net_R1L: single-layer ReLU RNN, B=4096, T=2048, NIN=3, NHID=5, NOUT=1
//
// Round 4: R3 analysis — warps stall ~66% of cycles. Two binds:
//   (a) fma-pipe rt: 40 FFMA/step x 2 cyc = 80 cyc/step floor (1 warp/SMSP).
//   (b) uncoalesced x loads: per-thread-private rows => every warp LDG.128
//       touches 32 distinct 128B lines (massive L1tex wavefront cost) and only
//       8 steps of prefetch cover vs 577-cyc DRAM latency.
// Fix (b): stage x through smem with cp.async.cg (L1-bypass, no reg staging).
// Tile = 32 steps (96 floats/row). Warp loads 32 rows coalesced (lanes 0..23
// fetch 24 consecutive float4 of one row), into padded smem (row stride 100
// floats -> conflict-free LDS.128: lane start bank = 4*lane). Double-buffered,
// one tile (~2600 cyc) of latency cover. Compute core: scalar FFMA (R3 form).

#define TT 2048
#define NINPUT 3
#define NH 5
#define TSTEPS 32                 // steps per tile
#define TFLOATS (TSTEPS * NINPUT) // 96 floats per row per tile
#define ROWSTRIDE 100             // padded row stride in floats (100 % 32 == 4)
#define NTILES (TT / TSTEPS)      // 64

static __device__ __forceinline__ void cp16(uint32_t saddr, const void* gaddr) {
    asm volatile("cp.async.cg.shared.global [%0], [%1], 16;"
                 :: "r"(saddr), "l"(gaddr) : "memory");
}
static __device__ __forceinline__ void cp_commit() {
    asm volatile("cp.async.commit_group;" ::: "memory");
}
static __device__ __forceinline__ void cp_wait1() {
    asm volatile("cp.async.wait_group 1;" ::: "memory");
}
static __device__ __forceinline__ void cp_wait0() {
    asm volatile("cp.async.wait_group 0;" ::: "memory");
}

struct Weights {
    float wih[NH][NINPUT];
    float whh[NH][NH];
    float c[NH];   // b_ih + b_hh
};

static __device__ __forceinline__ void rnn_step(
    const Weights& W, float x0, float x1, float x2, float h[NH])
{
    float a[NH];
#pragma unroll
    for (int j = 0; j < NH; j++) {
        float t = fmaf(x0, W.wih[j][0], W.c[j]);
        t = fmaf(x1, W.wih[j][1], t);
        t = fmaf(x2, W.wih[j][2], t);
        t = fmaf(h[0], W.whh[j][0], t);
        t = fmaf(h[1], W.whh[j][1], t);
        t = fmaf(h[2], W.whh[j][2], t);
        t = fmaf(h[3], W.whh[j][3], t);
        t = fmaf(h[4], W.whh[j][4], t);
        a[j] = t;
    }
#pragma unroll
    for (int j = 0; j < NH; j++) h[j] = fmaxf(a[j], 0.0f);
}

__global__ void __launch_bounds__(32, 1) rnn_relu_kernel(
    const float* __restrict__ state,   // [B, T, 3]
    const float* __restrict__ W_ih,    // [5, 3]
    const float* __restrict__ W_hh,    // [5, 5]
    const float* __restrict__ b_ih,    // [5]
    const float* __restrict__ b_hh,    // [5]
    const float* __restrict__ W_out,   // [1, 5]
    const float* __restrict__ b_out,   // [1]
    float* __restrict__ out,           // [B, 1]
    int B)
{
    __shared__ float sbuf[2][32][ROWSTRIDE];   // 2 x 32 x 100 floats = 25.6 KB

    const int lane  = threadIdx.x;
    const int bbase = blockIdx.x * 32;         // 32 consecutive batch rows/warp
    const int b     = bbase + lane;

    // ---- Weights (uniform; cached) ----
    Weights W;
#pragma unroll
    for (int j = 0; j < NH; j++) {
#pragma unroll
        for (int i = 0; i < NINPUT; i++) W.wih[j][i] = __ldg(&W_ih[j * NINPUT + i]);
#pragma unroll
        for (int k = 0; k < NH; k++) W.whh[j][k] = __ldg(&W_hh[j * NH + k]);
        W.c[j] = __ldg(&b_ih[j]) + __ldg(&b_hh[j]);
    }

    float h[NH];
#pragma unroll
    for (int k = 0; k < NH; k++) h[k] = 0.0f;

    // ---- Tile loader: warp cooperatively loads 32 rows x 96 floats,
    //      coalesced (lanes 0..23 -> 24 consecutive float4 per row). ----
    const bool ld_active = (lane < TFLOATS / 4);   // 24 lanes
    // smem byte address of sbuf[buf][r][lane*4]
    uint32_t s_base = (uint32_t)__cvta_generic_to_shared(&sbuf[0][0][0]);

    auto issue_tile = [&](int tile, int buf) {
        if (ld_active) {
            const float* g0 = state + (size_t)bbase * (TT * NINPUT)
                                    + (size_t)tile * TFLOATS + lane * 4;
            uint32_t s0 = s_base + (uint32_t)buf * (32 * ROWSTRIDE * 4) + lane * 16;
#pragma unroll
            for (int r = 0; r < 32; r++) {
                cp16(s0 + r * (ROWSTRIDE * 4), g0 + (size_t)r * (TT * NINPUT));
            }
        }
        cp_commit();
    };

    // Preload tile 0, start tile 1.
    issue_tile(0, 0);
    issue_tile(1, 1);

    for (int t = 0; t < NTILES; ++t) {
        const int cur = t & 1;

        // Wait: all groups except the most recent (tile t+1) -> tile t ready.
        if (t + 2 < NTILES) cp_wait1(); else cp_wait0();
        __syncwarp();

        // Compute 32 steps from sbuf[cur][lane][...]
        const float4* rowp = (const float4*)&sbuf[cur][lane][0];
#pragma unroll
        for (int s4 = 0; s4 < TSTEPS / 4; ++s4) {     // 8 groups of 4 steps
            const float4 f0 = rowp[s4 * 3 + 0];
            const float4 f1 = rowp[s4 * 3 + 1];
            const float4 f2 = rowp[s4 * 3 + 2];
            rnn_step(W, f0.x, f0.y, f0.z, h);
            rnn_step(W, f0.w, f1.x, f1.y, h);
            rnn_step(W, f1.z, f1.w, f2.x, h);
            rnn_step(W, f2.y, f2.z, f2.w, h);
        }

        __syncwarp();   // everyone done reading buf 'cur' before overwriting it

        // Prefetch tile t+2 into the buffer just freed.
        if (t + 2 < NTILES) issue_tile(t + 2, cur);
    }

    // ---- Readout: tanh(W_out @ h_T + b_out) ----
    float o = __ldg(&b_out[0]);
#pragma unroll
    for (int k = 0; k < NH; k++) o = fmaf(h[k], __ldg(&W_out[k]), o);
    out[b] = tanhf(o);
}

extern "C" void kernel_launch(void* const* d_in, const int* in_sizes, int n_in,
                              void* d_out, int out_size)
{
    const float* state = (const float*)d_in[0];
    const float* W_ih  = (const float*)d_in[1];
    const float* W_hh  = (const float*)d_in[2];
    const float* b_ih  = (const float*)d_in[3];
    const float* b_hh  = (const float*)d_in[4];
    const float* W_out = (const float*)d_in[5];
    const float* b_out = (const float*)d_in[6];
    float* out = (float*)d_out;

    const int B = in_sizes[0] / (TT * NINPUT);  // 4096
    const int threads = 32;
    const int blocks = B / threads;             // 128

    rnn_relu_kernel<<<blocks, threads>>>(state, W_ih, W_hh, b_ih, b_hh,
                                         W_out, b_out, out, B);
}